// round 4
// baseline (speedup 1.0000x reference)
#include <cuda_runtime.h>
#include <math.h>

#define EPSBN 1e-5f

__device__ float g_buf128[33554432];
__device__ float g_b64a[8388608];
__device__ float g_b64b[8388608];
__device__ float g_b64c[8388608];
__device__ float g_mean[256];
__device__ float g_istd[256];
__device__ float g_cnorm[512];
__device__ float g_fnorm[32768];
__device__ float g_cbT[131072];     // codebook transposed [k][j] = [256][512]
__device__ int   g_idx[32768];

#define BM 64
#define BN 64
#define BK 16

// ---------------- implicit-GEMM forward conv (two-level fp32 accumulation) ----
__global__ void __launch_bounds__(256) conv_gemm(
    const float* __restrict__ W, const float* __restrict__ X, float* __restrict__ Y,
    int CO, int CI, int KHW, int KW, int stride, int pad,
    int IH, int IW, int OH, int OW)
{
    const int Ktot = CI * KHW;
    __shared__ __align__(16) float As[BK][BM + 1];
    __shared__ __align__(16) float Bs[BK][BN];
    const int t = threadIdx.x, tx = t & 15, ty = t >> 4;
    const int am = t >> 4, ak = t & 15;
    const int pix0 = blockIdx.x * BN, co0 = blockIdx.y * BM;
    const int ohw = OH * OW, bv = t & (BN - 1);
    const int pixb = pix0 + bv, nb = pixb / ohw, remb = pixb - nb * ohw;
    const int oyb = remb / OW, oxb = remb - oyb * OW;
    const int iy0 = oyb * stride - pad, ix0 = oxb * stride - pad;
    const float* Xn = X + (size_t)nb * CI * IH * IW;
    float acc[4][4] = {};
    float tot[4][4] = {};
    int nch = 0;

    for (int k0 = 0; k0 < Ktot; k0 += BK) {
        #pragma unroll
        for (int i = 0; i < 4; i++) {
            int m = am + (i << 4), k = k0 + ak, co = co0 + m;
            float v = 0.f;
            if (co < CO && k < Ktot) v = W[co * Ktot + k];
            As[ak][m] = v;
        }
        #pragma unroll
        for (int i = 0; i < 4; i++) {
            int kk = (t >> 6) + (i << 2), k = k0 + kk;
            float v = 0.f;
            if (k < Ktot) {
                int ci = k / KHW, kr = k - ci * KHW, ky = kr / KW, kx = kr - ky * KW;
                int iy = iy0 + ky, ix = ix0 + kx;
                if ((unsigned)iy < (unsigned)IH && (unsigned)ix < (unsigned)IW)
                    v = Xn[(ci * IH + iy) * IW + ix];
            }
            Bs[kk][bv] = v;
        }
        __syncthreads();
        #pragma unroll
        for (int kk = 0; kk < BK; kk++) {
            float4 b = *(const float4*)&Bs[kk][tx << 2];
            #pragma unroll
            for (int i = 0; i < 4; i++) {
                float a = As[kk][(ty << 2) + i];
                acc[i][0] = fmaf(a, b.x, acc[i][0]);
                acc[i][1] = fmaf(a, b.y, acc[i][1]);
                acc[i][2] = fmaf(a, b.z, acc[i][2]);
                acc[i][3] = fmaf(a, b.w, acc[i][3]);
            }
        }
        __syncthreads();
        if (++nch == 4) {
            nch = 0;
            #pragma unroll
            for (int i = 0; i < 4; i++)
                #pragma unroll
                for (int j = 0; j < 4; j++) { tot[i][j] = __fadd_rn(tot[i][j], acc[i][j]); acc[i][j] = 0.f; }
        }
    }
    #pragma unroll
    for (int i = 0; i < 4; i++)
        #pragma unroll
        for (int j = 0; j < 4; j++) tot[i][j] = __fadd_rn(tot[i][j], acc[i][j]);

    #pragma unroll
    for (int j = 0; j < 4; j++) {
        int p = pix0 + (tx << 2) + j, n2 = p / ohw, r2 = p - n2 * ohw;
        int oy2 = r2 / OW, ox2 = r2 - oy2 * OW;
        #pragma unroll
        for (int i = 0; i < 4; i++) {
            int co = co0 + (ty << 2) + i;
            if (co < CO) Y[((n2 * CO + co) * OH + oy2) * OW + ox2] = tot[i][j];
        }
    }
}

// ---------------- ConvTranspose2d(k=4,s=2,p=1) parity-split implicit GEMM ------
__global__ void __launch_bounds__(256) convt_gemm(
    const float* __restrict__ W, const float* __restrict__ X, float* __restrict__ Y,
    int CO, int CI, int IH, int IW, int OH, int OW)
{
    const int py = (blockIdx.z >> 1) & 1, px = blockIdx.z & 1;
    const int ky0v = 1 - py, ky1v = 3 - py, oy0v = py, oy1v = py - 1;
    const int kx0v = 1 - px, kx1v = 3 - px, ox0v = px, ox1v = px - 1;
    const int Ktot = CI * 4;
    __shared__ __align__(16) float As[BK][BM + 1];
    __shared__ __align__(16) float Bs[BK][BN];
    const int t = threadIdx.x, tx = t & 15, ty = t >> 4;
    const int am = t >> 4, ak = t & 15;
    const int pix0 = blockIdx.x * BN, co0 = blockIdx.y * BM;
    const int yhw = IH * IW, bv = t & (BN - 1);
    const int pixb = pix0 + bv, nb = pixb / yhw, remb = pixb - nb * yhw;
    const int yb = remb / IW, xb = remb - yb * IW;
    const float* Xn = X + (size_t)nb * CI * yhw;
    float acc[4][4] = {};

    for (int k0 = 0; k0 < Ktot; k0 += BK) {
        #pragma unroll
        for (int i = 0; i < 4; i++) {
            int m = am + (i << 4), k = k0 + ak;
            int ci = k >> 2, tt = k & 3;
            int ky = (tt & 2) ? ky1v : ky0v, kx = (tt & 1) ? kx1v : kx0v;
            int co = co0 + m;
            As[ak][m] = (co < CO) ? W[((ci * CO + co) << 4) + (ky << 2) + kx] : 0.f;
        }
        #pragma unroll
        for (int i = 0; i < 4; i++) {
            int kk = (t >> 6) + (i << 2), k = k0 + kk;
            int ci = k >> 2, tt = k & 3;
            int iy = yb + ((tt & 2) ? oy1v : oy0v);
            int ix = xb + ((tt & 1) ? ox1v : ox0v);
            float v = 0.f;
            if ((unsigned)iy < (unsigned)IH && (unsigned)ix < (unsigned)IW)
                v = Xn[(ci * IH + iy) * IW + ix];
            Bs[kk][bv] = v;
        }
        __syncthreads();
        #pragma unroll
        for (int kk = 0; kk < BK; kk++) {
            float4 b = *(const float4*)&Bs[kk][tx << 2];
            #pragma unroll
            for (int i = 0; i < 4; i++) {
                float a = As[kk][(ty << 2) + i];
                acc[i][0] = fmaf(a, b.x, acc[i][0]);
                acc[i][1] = fmaf(a, b.y, acc[i][1]);
                acc[i][2] = fmaf(a, b.z, acc[i][2]);
                acc[i][3] = fmaf(a, b.w, acc[i][3]);
            }
        }
        __syncthreads();
    }
    #pragma unroll
    for (int j = 0; j < 4; j++) {
        int p = pix0 + (tx << 2) + j, n2 = p / yhw, r2 = p - n2 * yhw;
        int y2 = r2 / IW, x2 = r2 - y2 * IW;
        int oy = (y2 << 1) + py, ox = (x2 << 1) + px;
        #pragma unroll
        for (int i = 0; i < 4; i++) {
            int co = co0 + (ty << 2) + i;
            if (co < CO) Y[((n2 * CO + co) * OH + oy) * OW + ox] = acc[i][j];
        }
    }
}

// ---------------- direct ConvTranspose for CO=3 (d_t2) ----------------
__global__ void __launch_bounds__(256) convt_direct(
    const float* __restrict__ W, const float* __restrict__ X, float* __restrict__ Y,
    int CO, int CI, int IH, int IW, int OH, int OW)
{
    int ox = threadIdx.x, oy = blockIdx.x, co = blockIdx.y, n = blockIdx.z;
    int kys[2], iys[2], nky = 0;
    #pragma unroll
    for (int ky = 0; ky < 4; ky++) {
        int u = oy + 1 - ky;
        if ((u & 1) == 0) { int iy = u >> 1; if (iy >= 0 && iy < IH) { kys[nky] = ky; iys[nky] = iy; nky++; } }
    }
    int kxs[2], ixs[2], nkx = 0;
    #pragma unroll
    for (int kx = 0; kx < 4; kx++) {
        int u = ox + 1 - kx;
        if ((u & 1) == 0) { int ix = u >> 1; if (ix >= 0 && ix < IW) { kxs[nkx] = kx; ixs[nkx] = ix; nkx++; } }
    }
    float acc = 0.f;
    for (int ci = 0; ci < CI; ci++) {
        const float* xc = X + ((size_t)n * CI + ci) * IH * IW;
        const float* wc = W + ((size_t)ci * CO + co) * 16;
        for (int a = 0; a < nky; a++)
            for (int b2 = 0; b2 < nkx; b2++)
                acc = fmaf(xc[iys[a] * IW + ixs[b2]], wc[kys[a] * 4 + kxs[b2]], acc);
    }
    Y[(((size_t)n * CO + co) * OH + oy) * OW + ox] = acc;
}

// ---------------- BatchNorm stats: fp32 Kahan ----------------
__global__ void bn_stats(const float* __restrict__ x, const float* __restrict__ r,
                         float* __restrict__ mean, float* __restrict__ istd,
                         int C, int HW, int Bn)
{
    int c = blockIdx.x;
    float s = 0.f, cs = 0.f, ss = 0.f, css = 0.f;
    for (int n = 0; n < Bn; n++) {
        const float* p = x + (size_t)(n * C + c) * HW;
        const float* q = r ? r + (size_t)(n * C + c) * HW : (const float*)0;
        for (int i = threadIdx.x; i < HW; i += blockDim.x) {
            float v = p[i];
            if (q) v = __fadd_rn(v, q[i]);
            float y1 = __fsub_rn(v, cs);
            float t1 = __fadd_rn(s, y1);
            cs = __fsub_rn(__fsub_rn(t1, s), y1); s = t1;
            float w = __fmul_rn(v, v);
            float y2 = __fsub_rn(w, css);
            float t2 = __fadd_rn(ss, y2);
            css = __fsub_rn(__fsub_rn(t2, ss), y2); ss = t2;
        }
    }
    s = __fsub_rn(s, cs); ss = __fsub_rn(ss, css);
    __shared__ float shs[32], shss[32];
    int lane = threadIdx.x & 31, wid = threadIdx.x >> 5;
    #pragma unroll
    for (int o = 16; o > 0; o >>= 1) {
        s  += __shfl_down_sync(0xffffffffu, s,  o);
        ss += __shfl_down_sync(0xffffffffu, ss, o);
    }
    if (lane == 0) { shs[wid] = s; shss[wid] = ss; }
    __syncthreads();
    if (threadIdx.x == 0) {
        int nw = blockDim.x >> 5;
        float ts = 0.f, tss = 0.f;
        for (int i = 0; i < nw; i++) { ts += shs[i]; tss += shss[i]; }
        float inv = 1.f / ((float)Bn * (float)HW);
        float m = ts * inv;
        float var = fmaxf(tss * inv - m * m, 0.f);
        mean[c] = m;
        istd[c] = rsqrtf(var + EPSBN);
    }
}

// mode: 0 none, 1 relu, 2 tanh; optional residual r added pre-norm.
__global__ void bn_apply(const float* __restrict__ x, const float* __restrict__ r,
                         float* __restrict__ y,
                         const float* __restrict__ g, const float* __restrict__ b,
                         const float* __restrict__ mean, const float* __restrict__ istd,
                         int C, int HW, int total, int mode)
{
    int stride = gridDim.x * blockDim.x;
    for (int i = blockIdx.x * blockDim.x + threadIdx.x; i < total; i += stride) {
        int c = (i / HW) % C;
        float v = x[i];
        if (r) v = __fadd_rn(v, r[i]);
        v = __fadd_rn(__fmul_rn(__fmul_rn(g[c], __fsub_rn(v, mean[c])), istd[c]), b[c]);
        if (mode == 1)      v = fmaxf(v, 0.f);
        else if (mode == 2) v = tanhf(v);
        y[i] = v;
    }
}

// ---------------- VQ: exact-fp32 distances, reference epilogue bit-structure ---
__global__ void transpose_cb(const float* __restrict__ cb, float* __restrict__ cbT)
{
    int i = blockIdx.x * blockDim.x + threadIdx.x;        // 131072
    int j = i >> 8, k = i & 255;
    cbT[k * 512 + j] = cb[i];
}

__global__ void cnorm_k(const float* __restrict__ cb, float* __restrict__ cn)
{
    int j = blockIdx.x * blockDim.x + threadIdx.x;
    if (j < 512) {
        float s = 0.f;
        const float* p = cb + j * 256;
        for (int c = 0; c < 256; c++) s = __fadd_rn(s, __fmul_rn(p[c], p[c]));
        cn[j] = s;
    }
}

__global__ void fnorm_k(const float* __restrict__ ze, float* __restrict__ fn, int HW)
{   // grid-multiple shifts of S translate all d_j uniformly -> ranking-safe
    int w = (blockIdx.x * blockDim.x + threadIdx.x) >> 5;
    int lane = threadIdx.x & 31;
    int n = w / HW, hw = w - n * HW;
    const float* base = ze + (size_t)n * 256 * HW + hw;
    float s = 0.f;
    for (int k = lane; k < 256; k += 32) {
        float v = base[(size_t)k * HW];
        s = __fadd_rn(s, __fmul_rn(v, v));
    }
    #pragma unroll
    for (int o = 16; o > 0; o >>= 1) s += __shfl_down_sync(0xffffffffu, s, o);
    if (lane == 0) fn[w] = s;
}

// 64 pixels x 512 codes per block; accurate fp32 mm (error ~1e-8 << half-grid
// 1.5e-5), then d = fl(fl(S - 2*mm) + cn), first-index argmin (strict <).
#define VQ_KC 16
__global__ void __launch_bounds__(512) vq_dist_argmin(
    const float* __restrict__ ze, const float* __restrict__ cbT,
    const float* __restrict__ cn, const float* __restrict__ fnorm,
    int* __restrict__ idx, int HW)
{
    __shared__ float fs[64 * 17];
    __shared__ __align__(16) float cbs[VQ_KC * 512];
    __shared__ float cns[512];
    __shared__ float rd[64 * 8];
    __shared__ int   rj[64 * 8];

    const int t = threadIdx.x, px = t & 63, jg = t >> 6;
    const int p = blockIdx.x * 64 + px;
    cns[t] = cn[t];

    float acc[64];
    #pragma unroll
    for (int j = 0; j < 64; j++) acc[j] = 0.f;

    for (int k0 = 0; k0 < 256; k0 += VQ_KC) {
        __syncthreads();
        for (int i = t; i < 64 * VQ_KC; i += 512) {
            int kk = i >> 6, pp = i & 63;
            int gp = blockIdx.x * 64 + pp;
            int gn = gp / HW, ghw = gp - gn * HW;
            fs[pp * 17 + kk] = ze[((size_t)gn * 256 + (k0 + kk)) * HW + ghw];
        }
        for (int i = t; i < VQ_KC * 512; i += 512)
            cbs[i] = cbT[(size_t)(k0 + (i >> 9)) * 512 + (i & 511)];
        __syncthreads();

        float fv[VQ_KC];
        #pragma unroll
        for (int kk = 0; kk < VQ_KC; kk++) fv[kk] = fs[px * 17 + kk];

        #pragma unroll
        for (int j4 = 0; j4 < 16; j4++) {
            float a0, a1, a2, a3;
            {
                float4 c = *(const float4*)&cbs[jg * 64 + j4 * 4];
                a0 = __fmul_rn(fv[0], c.x); a1 = __fmul_rn(fv[0], c.y);
                a2 = __fmul_rn(fv[0], c.z); a3 = __fmul_rn(fv[0], c.w);
                #pragma unroll
                for (int kk = 1; kk < 8; kk++) {
                    float4 d = *(const float4*)&cbs[kk * 512 + jg * 64 + j4 * 4];
                    a0 = fmaf(fv[kk], d.x, a0); a1 = fmaf(fv[kk], d.y, a1);
                    a2 = fmaf(fv[kk], d.z, a2); a3 = fmaf(fv[kk], d.w, a3);
                }
                acc[j4*4+0] = __fadd_rn(acc[j4*4+0], a0);
                acc[j4*4+1] = __fadd_rn(acc[j4*4+1], a1);
                acc[j4*4+2] = __fadd_rn(acc[j4*4+2], a2);
                acc[j4*4+3] = __fadd_rn(acc[j4*4+3], a3);
            }
            {
                float4 c = *(const float4*)&cbs[8 * 512 + jg * 64 + j4 * 4];
                a0 = __fmul_rn(fv[8], c.x); a1 = __fmul_rn(fv[8], c.y);
                a2 = __fmul_rn(fv[8], c.z); a3 = __fmul_rn(fv[8], c.w);
                #pragma unroll
                for (int kk = 9; kk < 16; kk++) {
                    float4 d = *(const float4*)&cbs[kk * 512 + jg * 64 + j4 * 4];
                    a0 = fmaf(fv[kk], d.x, a0); a1 = fmaf(fv[kk], d.y, a1);
                    a2 = fmaf(fv[kk], d.z, a2); a3 = fmaf(fv[kk], d.w, a3);
                }
                acc[j4*4+0] = __fadd_rn(acc[j4*4+0], a0);
                acc[j4*4+1] = __fadd_rn(acc[j4*4+1], a1);
                acc[j4*4+2] = __fadd_rn(acc[j4*4+2], a2);
                acc[j4*4+3] = __fadd_rn(acc[j4*4+3], a3);
            }
        }
    }

    float S = fnorm[p];
    float best = 3.4028235e38f;
    int bj = 0;
    #pragma unroll
    for (int j = 0; j < 64; j++) {
        float q = __fsub_rn(S, __fmul_rn(2.0f, acc[j]));
        float dj = __fadd_rn(q, cns[jg * 64 + j]);
        if (dj < best) { best = dj; bj = jg * 64 + j; }
    }
    rd[px * 8 + jg] = best;
    rj[px * 8 + jg] = bj;
    __syncthreads();
    if (t < 64) {
        float bb = rd[t * 8]; int jj = rj[t * 8];
        #pragma unroll
        for (int gsel = 1; gsel < 8; gsel++) {
            float d2 = rd[t * 8 + gsel];
            if (d2 < bb) { bb = d2; jj = rj[t * 8 + gsel]; }
        }
        idx[blockIdx.x * 64 + t] = jj;
    }
}

__global__ void vq_gather(const int* __restrict__ idx, const float* __restrict__ cb,
                          float* __restrict__ zq, int HW, int total)
{
    int stride = gridDim.x * blockDim.x;
    for (int i = blockIdx.x * blockDim.x + threadIdx.x; i < total; i += stride) {
        int hw = i % HW, nc = i / HW, c = nc & 255, n = nc >> 8;
        zq[i] = cb[idx[n * HW + hw] * 256 + c];
    }
}

// ---------------- pipeline ----------------
extern "C" void kernel_launch(void* const* d_in, const int* in_sizes, int n_in,
                              void* d_out, int out_size)
{
    const float* img  = (const float*)d_in[0];
    const float* e_w1 = (const float*)d_in[1];
    const float* e_g1 = (const float*)d_in[2];
    const float* e_b1 = (const float*)d_in[3];
    const float* e_w2 = (const float*)d_in[4];
    const float* e_g2 = (const float*)d_in[5];
    const float* e_b2 = (const float*)d_in[6];
    const float* e_w3 = (const float*)d_in[7];
    const float* e_g3 = (const float*)d_in[8];
    const float* e_b3 = (const float*)d_in[9];
    const float* e_w4 = (const float*)d_in[10];
    const float* e_g4 = (const float*)d_in[12];
    const float* e_b4 = (const float*)d_in[13];
    const float* e_g5 = (const float*)d_in[14];
    const float* e_b5 = (const float*)d_in[15];
    const float* cb   = (const float*)d_in[16];
    const float* dw1  = (const float*)d_in[17];
    const float* dg1  = (const float*)d_in[18];
    const float* db1  = (const float*)d_in[19];
    const float* dw2  = (const float*)d_in[20];
    const float* dg2  = (const float*)d_in[21];
    const float* db2  = (const float*)d_in[22];
    const float* dg3  = (const float*)d_in[23];
    const float* db3  = (const float*)d_in[24];
    const float* dt1  = (const float*)d_in[25];
    const float* dg4  = (const float*)d_in[26];
    const float* db4  = (const float*)d_in[27];
    const float* dt2  = (const float*)d_in[28];
    const float* dg5  = (const float*)d_in[30];
    const float* db5  = (const float*)d_in[31];
    float* out = (float*)d_out;

    float *buf128, *b64a, *b64b, *b64c, *mean, *istd, *cnorm, *fnorm, *cbT;
    int* idx;
    cudaGetSymbolAddress((void**)&buf128, g_buf128);
    cudaGetSymbolAddress((void**)&b64a,   g_b64a);
    cudaGetSymbolAddress((void**)&b64b,   g_b64b);
    cudaGetSymbolAddress((void**)&b64c,   g_b64c);
    cudaGetSymbolAddress((void**)&mean,   g_mean);
    cudaGetSymbolAddress((void**)&istd,   g_istd);
    cudaGetSymbolAddress((void**)&cnorm,  g_cnorm);
    cudaGetSymbolAddress((void**)&fnorm,  g_fnorm);
    cudaGetSymbolAddress((void**)&cbT,    g_cbT);
    cudaGetSymbolAddress((void**)&idx,    g_idx);

    const int T128 = 33554432, T64 = 8388608;

    // ---- encoder ----
    conv_gemm<<<dim3(2048, 4), 256>>>(e_w1, img, buf128, 256, 3, 16, 4, 2, 1, 256, 256, 128, 128);
    bn_stats<<<256, 256>>>(buf128, (const float*)0, mean, istd, 256, 16384, 8);
    bn_apply<<<16384, 256>>>(buf128, (const float*)0, buf128, e_g1, e_b1, mean, istd, 256, 16384, T128, 1);

    conv_gemm<<<dim3(512, 4), 256>>>(e_w2, buf128, b64a, 256, 256, 16, 4, 2, 1, 128, 128, 64, 64);
    bn_stats<<<256, 256>>>(b64a, (const float*)0, mean, istd, 256, 4096, 8);
    bn_apply<<<8192, 256>>>(b64a, (const float*)0, b64a, e_g2, e_b2, mean, istd, 256, 4096, T64, 1);

    conv_gemm<<<dim3(512, 4), 256>>>(e_w3, b64a, b64b, 256, 256, 9, 3, 1, 1, 64, 64, 64, 64);
    bn_stats<<<256, 256>>>(b64b, (const float*)0, mean, istd, 256, 4096, 8);
    bn_apply<<<8192, 256>>>(b64b, (const float*)0, b64b, e_g3, e_b3, mean, istd, 256, 4096, T64, 1);

    conv_gemm<<<dim3(512, 4), 256>>>(e_w4, b64b, b64c, 256, 256, 1, 1, 1, 0, 64, 64, 64, 64);
    bn_stats<<<256, 256>>>(b64c, (const float*)0, mean, istd, 256, 4096, 8);
    bn_apply<<<8192, 256>>>(b64c, (const float*)0, b64c, e_g4, e_b4, mean, istd, 256, 4096, T64, 1);

    bn_stats<<<256, 256>>>(b64a, b64c, mean, istd, 256, 4096, 8);
    bn_apply<<<8192, 256>>>(b64a, b64c, b64b, e_g5, e_b5, mean, istd, 256, 4096, T64, 0);

    // ---- VQ ----
    transpose_cb<<<512, 256>>>(cb, cbT);
    cnorm_k<<<2, 256>>>(cb, cnorm);
    fnorm_k<<<4096, 256>>>(b64b, fnorm, 4096);
    vq_dist_argmin<<<512, 512>>>(b64b, cbT, cnorm, fnorm, idx, 4096);
    vq_gather<<<8192, 256>>>(idx, cb, b64c, 4096, T64);

    // ---- decoder ----
    conv_gemm<<<dim3(512, 4), 256>>>(dw1, b64c, b64a, 256, 256, 9, 3, 1, 1, 64, 64, 64, 64);
    bn_stats<<<256, 256>>>(b64a, (const float*)0, mean, istd, 256, 4096, 8);
    bn_apply<<<8192, 256>>>(b64a, (const float*)0, b64a, dg1, db1, mean, istd, 256, 4096, T64, 1);

    conv_gemm<<<dim3(512, 4), 256>>>(dw2, b64a, b64b, 256, 256, 1, 1, 1, 0, 64, 64, 64, 64);
    bn_stats<<<256, 256>>>(b64b, (const float*)0, mean, istd, 256, 4096, 8);
    bn_apply<<<8192, 256>>>(b64b, (const float*)0, b64b, dg2, db2, mean, istd, 256, 4096, T64, 1);

    bn_stats<<<256, 256>>>(b64c, b64b, mean, istd, 256, 4096, 8);
    bn_apply<<<8192, 256>>>(b64c, b64b, b64a, dg3, db3, mean, istd, 256, 4096, T64, 1);

    convt_gemm<<<dim3(512, 4, 4), 256>>>(dt1, b64a, buf128, 256, 256, 64, 64, 128, 128);
    bn_stats<<<256, 256>>>(buf128, (const float*)0, mean, istd, 256, 16384, 8);
    bn_apply<<<16384, 256>>>(buf128, (const float*)0, buf128, dg4, db4, mean, istd, 256, 16384, T128, 1);

    convt_direct<<<dim3(256, 3, 8), 256>>>(dt2, buf128, out, 3, 256, 128, 128, 256, 256);
    bn_stats<<<3, 256>>>(out, (const float*)0, mean, istd, 3, 65536, 8);
    bn_apply<<<1536, 256>>>(out, (const float*)0, out, dg5, db5, mean, istd, 3, 65536, 1572864, 2);
}

// round 5
// speedup vs baseline: 1.2528x; 1.2528x over previous
#include <cuda_runtime.h>
#include <math.h>

#define EPSBN 1e-5f

__device__ float g_buf128[33554432];
__device__ float g_b64a[8388608];
__device__ float g_b64b[8388608];
__device__ float g_b64c[8388608];
__device__ float g_mean[256];
__device__ float g_istd[256];
__device__ float g_cnorm[512];
__device__ float g_fnorm[32768];
__device__ float g_cbT[131072];
__device__ int   g_idx[32768];

// ---------------- 128x128x8 implicit-GEMM forward conv --------------------
// Numerics: accumulator folded into tot every 8 tiles (=64 k) -> bit-identical
// FMA chains to the round-4 kernel (fold every 4 BK16 tiles). DO NOT CHANGE:
// z_e bits feed the VQ argmin.
__global__ void __launch_bounds__(256, 2) conv_gemm128(
    const float* __restrict__ W, const float* __restrict__ X, float* __restrict__ Y,
    int CO, int CI, int KHW, int KW, int stride, int pad,
    int IH, int IW, int OH, int OW)
{
    const int Ktot = CI * KHW;
    __shared__ __align__(16) float As[8][128];
    __shared__ __align__(16) float Bs[8][128];
    const int t = threadIdx.x;
    const int pix0 = blockIdx.x * 128, co0 = blockIdx.y * 128;
    const int ohw = OH * OW;

    const int acol = t >> 1;
    const int akq  = (t & 1) << 2;
    const float* Wrow = W + (size_t)(co0 + acol) * Ktot + akq;

    const int bpv = t & 127;
    const int bkq = (t >> 7) << 2;
    const int pixb = pix0 + bpv;
    const int nb = pixb / ohw, remb = pixb - nb * ohw;
    const int oyb = remb / OW, oxb = remb - oyb * OW;
    const int iy0 = oyb * stride - pad, ix0 = oxb * stride - pad;
    const float* Xn = X + (size_t)nb * CI * IH * IW;

    const int tx = t & 15, ty = t >> 4;
    float acc[8][8] = {};
    float tot[8][8] = {};
    int nch = 0;

    for (int k0 = 0; k0 < Ktot; k0 += 8) {
        float4 wv = *(const float4*)(Wrow + k0);
        float bval[4];
        #pragma unroll
        for (int i = 0; i < 4; i++) {
            int k = k0 + bkq + i;
            int ci = k / KHW, kr = k - ci * KHW, ky = kr / KW, kx = kr - ky * KW;
            int iy = iy0 + ky, ix = ix0 + kx;
            float v = 0.f;
            if ((unsigned)iy < (unsigned)IH && (unsigned)ix < (unsigned)IW)
                v = Xn[(ci * IH + iy) * IW + ix];
            bval[i] = v;
        }
        As[akq + 0][acol] = wv.x;
        As[akq + 1][acol] = wv.y;
        As[akq + 2][acol] = wv.z;
        As[akq + 3][acol] = wv.w;
        #pragma unroll
        for (int i = 0; i < 4; i++) Bs[bkq + i][bpv] = bval[i];
        __syncthreads();
        #pragma unroll
        for (int kk = 0; kk < 8; kk++) {
            float4 a0 = *(const float4*)&As[kk][ty << 2];
            float4 a1 = *(const float4*)&As[kk][64 + (ty << 2)];
            float4 b0 = *(const float4*)&Bs[kk][tx << 2];
            float4 b1 = *(const float4*)&Bs[kk][64 + (tx << 2)];
            float av[8] = {a0.x, a0.y, a0.z, a0.w, a1.x, a1.y, a1.z, a1.w};
            float bv[8] = {b0.x, b0.y, b0.z, b0.w, b1.x, b1.y, b1.z, b1.w};
            #pragma unroll
            for (int i = 0; i < 8; i++)
                #pragma unroll
                for (int j = 0; j < 8; j++)
                    acc[i][j] = fmaf(av[i], bv[j], acc[i][j]);
        }
        __syncthreads();
        if (++nch == 8) {            // fold every 64 k (bit-matches round 4)
            nch = 0;
            #pragma unroll
            for (int i = 0; i < 8; i++)
                #pragma unroll
                for (int j = 0; j < 8; j++) {
                    tot[i][j] = __fadd_rn(tot[i][j], acc[i][j]);
                    acc[i][j] = 0.f;
                }
        }
    }
    #pragma unroll
    for (int i = 0; i < 8; i++)
        #pragma unroll
        for (int j = 0; j < 8; j++) tot[i][j] = __fadd_rn(tot[i][j], acc[i][j]);

    #pragma unroll
    for (int j = 0; j < 8; j++) {
        int pj = (j < 4) ? (tx << 2) + j : 64 + (tx << 2) + (j - 4);
        int p = pix0 + pj;
        int n2 = p / ohw, r2 = p - n2 * ohw;
        int oy2 = r2 / OW, ox2 = r2 - oy2 * OW;
        size_t base = (size_t)n2 * CO * ohw + (size_t)oy2 * OW + ox2;
        #pragma unroll
        for (int i = 0; i < 8; i++) {
            int co = co0 + ((i < 4) ? (ty << 2) + i : 64 + (ty << 2) + (i - 4));
            Y[base + (size_t)co * ohw] = tot[i][j];
        }
    }
}

// ---------------- ConvTranspose2d(k=4,s=2,p=1) parity-split, 128x128x8 --------
__global__ void __launch_bounds__(256, 2) convt_gemm128(
    const float* __restrict__ W, const float* __restrict__ X, float* __restrict__ Y,
    int CO, int CI, int IH, int IW, int OH, int OW)
{
    const int py = (blockIdx.z >> 1) & 1, px = blockIdx.z & 1;
    const int ky0 = 1 - py, ky1 = 3 - py, dy0 = py, dy1 = py - 1;
    const int kx0 = 1 - px, kx1 = 3 - px, dx0 = px, dx1 = px - 1;
    const int Ktot = CI * 4;
    __shared__ __align__(16) float As[8][128];
    __shared__ __align__(16) float Bs[8][128];
    const int t = threadIdx.x;
    const int pix0 = blockIdx.x * 128, co0 = blockIdx.y * 128;
    const int yhw = IH * IW;

    const int acol = t >> 1;
    const int akq  = (t & 1) << 2;
    const int bpv = t & 127;
    const int bkq = (t >> 7) << 2;
    const int pixb = pix0 + bpv;
    const int nb = pixb / yhw, remb = pixb - nb * yhw;
    const int yb = remb / IW, xb = remb - yb * IW;
    const float* Xn = X + (size_t)nb * CI * yhw;

    const int tx = t & 15, ty = t >> 4;
    float acc[8][8] = {};

    for (int k0 = 0; k0 < Ktot; k0 += 8) {
        int ci_a = (k0 + akq) >> 2;
        const float* wb = W + (((size_t)ci_a * CO + co0 + acol) << 4);
        float w0 = wb[ky0 * 4 + kx0];
        float w1 = wb[ky0 * 4 + kx1];
        float w2 = wb[ky1 * 4 + kx0];
        float w3 = wb[ky1 * 4 + kx1];
        float bval[4];
        #pragma unroll
        for (int i = 0; i < 4; i++) {
            int k = k0 + bkq + i;
            int ci = k >> 2, tt = k & 3;
            int iy = yb + ((tt & 2) ? dy1 : dy0);
            int ix = xb + ((tt & 1) ? dx1 : dx0);
            float v = 0.f;
            if ((unsigned)iy < (unsigned)IH && (unsigned)ix < (unsigned)IW)
                v = Xn[(ci * IH + iy) * IW + ix];
            bval[i] = v;
        }
        As[akq + 0][acol] = w0;
        As[akq + 1][acol] = w1;
        As[akq + 2][acol] = w2;
        As[akq + 3][acol] = w3;
        #pragma unroll
        for (int i = 0; i < 4; i++) Bs[bkq + i][bpv] = bval[i];
        __syncthreads();
        #pragma unroll
        for (int kk = 0; kk < 8; kk++) {
            float4 a0 = *(const float4*)&As[kk][ty << 2];
            float4 a1 = *(const float4*)&As[kk][64 + (ty << 2)];
            float4 b0 = *(const float4*)&Bs[kk][tx << 2];
            float4 b1 = *(const float4*)&Bs[kk][64 + (tx << 2)];
            float av[8] = {a0.x, a0.y, a0.z, a0.w, a1.x, a1.y, a1.z, a1.w};
            float bv[8] = {b0.x, b0.y, b0.z, b0.w, b1.x, b1.y, b1.z, b1.w};
            #pragma unroll
            for (int i = 0; i < 8; i++)
                #pragma unroll
                for (int j = 0; j < 8; j++)
                    acc[i][j] = fmaf(av[i], bv[j], acc[i][j]);
        }
        __syncthreads();
    }

    #pragma unroll
    for (int j = 0; j < 8; j++) {
        int pj = (j < 4) ? (tx << 2) + j : 64 + (tx << 2) + (j - 4);
        int p = pix0 + pj;
        int n2 = p / yhw, r2 = p - n2 * yhw;
        int y2 = r2 / IW, x2 = r2 - y2 * IW;
        int oy = (y2 << 1) + py, ox = (x2 << 1) + px;
        size_t base = ((size_t)n2 * CO) * OH * OW + (size_t)oy * OW + ox;
        #pragma unroll
        for (int i = 0; i < 8; i++) {
            int co = co0 + ((i < 4) ? (ty << 2) + i : 64 + (ty << 2) + (i - 4));
            Y[base + (size_t)co * OH * OW] = acc[i][j];
        }
    }
}

// ---------------- direct ConvTranspose for CO=3 (d_t2) ----------------
__global__ void __launch_bounds__(256) convt_direct(
    const float* __restrict__ W, const float* __restrict__ X, float* __restrict__ Y,
    int CO, int CI, int IH, int IW, int OH, int OW)
{
    int ox = threadIdx.x, oy = blockIdx.x, co = blockIdx.y, n = blockIdx.z;
    int kys[2], iys[2], nky = 0;
    #pragma unroll
    for (int ky = 0; ky < 4; ky++) {
        int u = oy + 1 - ky;
        if ((u & 1) == 0) { int iy = u >> 1; if (iy >= 0 && iy < IH) { kys[nky] = ky; iys[nky] = iy; nky++; } }
    }
    int kxs[2], ixs[2], nkx = 0;
    #pragma unroll
    for (int kx = 0; kx < 4; kx++) {
        int u = ox + 1 - kx;
        if ((u & 1) == 0) { int ix = u >> 1; if (ix >= 0 && ix < IW) { kxs[nkx] = kx; ixs[nkx] = ix; nkx++; } }
    }
    float acc = 0.f;
    for (int ci = 0; ci < CI; ci++) {
        const float* xc = X + ((size_t)n * CI + ci) * IH * IW;
        const float* wc = W + ((size_t)ci * CO + co) * 16;
        for (int a = 0; a < nky; a++)
            for (int b2 = 0; b2 < nkx; b2++)
                acc = fmaf(xc[iys[a] * IW + ixs[b2]], wc[kys[a] * 4 + kxs[b2]], acc);
    }
    Y[(((size_t)n * CO + co) * OH + oy) * OW + ox] = acc;
}

// ---------------- BatchNorm stats: fp32 Kahan ----------------
__global__ void bn_stats(const float* __restrict__ x, const float* __restrict__ r,
                         float* __restrict__ mean, float* __restrict__ istd,
                         int C, int HW, int Bn)
{
    int c = blockIdx.x;
    float s = 0.f, cs = 0.f, ss = 0.f, css = 0.f;
    for (int n = 0; n < Bn; n++) {
        const float* p = x + (size_t)(n * C + c) * HW;
        const float* q = r ? r + (size_t)(n * C + c) * HW : (const float*)0;
        for (int i = threadIdx.x; i < HW; i += blockDim.x) {
            float v = p[i];
            if (q) v = __fadd_rn(v, q[i]);
            float y1 = __fsub_rn(v, cs);
            float t1 = __fadd_rn(s, y1);
            cs = __fsub_rn(__fsub_rn(t1, s), y1); s = t1;
            float w = __fmul_rn(v, v);
            float y2 = __fsub_rn(w, css);
            float t2 = __fadd_rn(ss, y2);
            css = __fsub_rn(__fsub_rn(t2, ss), y2); ss = t2;
        }
    }
    s = __fsub_rn(s, cs); ss = __fsub_rn(ss, css);
    __shared__ float shs[32], shss[32];
    int lane = threadIdx.x & 31, wid = threadIdx.x >> 5;
    #pragma unroll
    for (int o = 16; o > 0; o >>= 1) {
        s  += __shfl_down_sync(0xffffffffu, s,  o);
        ss += __shfl_down_sync(0xffffffffu, ss, o);
    }
    if (lane == 0) { shs[wid] = s; shss[wid] = ss; }
    __syncthreads();
    if (threadIdx.x == 0) {
        int nw = blockDim.x >> 5;
        float ts = 0.f, tss = 0.f;
        for (int i = 0; i < nw; i++) { ts += shs[i]; tss += shss[i]; }
        float inv = 1.f / ((float)Bn * (float)HW);
        float m = ts * inv;
        float var = fmaxf(tss * inv - m * m, 0.f);
        mean[c] = m;
        istd[c] = rsqrtf(var + EPSBN);
    }
}

__global__ void bn_apply(const float* __restrict__ x, const float* __restrict__ r,
                         float* __restrict__ y,
                         const float* __restrict__ g, const float* __restrict__ b,
                         const float* __restrict__ mean, const float* __restrict__ istd,
                         int C, int HW, int total, int mode)
{
    int stride = gridDim.x * blockDim.x;
    for (int i = blockIdx.x * blockDim.x + threadIdx.x; i < total; i += stride) {
        int c = (i / HW) % C;
        float v = x[i];
        if (r) v = __fadd_rn(v, r[i]);
        v = __fadd_rn(__fmul_rn(__fmul_rn(g[c], __fsub_rn(v, mean[c])), istd[c]), b[c]);
        if (mode == 1)      v = fmaxf(v, 0.f);
        else if (mode == 2) v = tanhf(v);
        y[i] = v;
    }
}

// ---------------- VQ (FROZEN: bit-exact path validated in round 4) ----------
__global__ void transpose_cb(const float* __restrict__ cb, float* __restrict__ cbT)
{
    int i = blockIdx.x * blockDim.x + threadIdx.x;
    int j = i >> 8, k = i & 255;
    cbT[k * 512 + j] = cb[i];
}

__global__ void cnorm_k(const float* __restrict__ cb, float* __restrict__ cn)
{
    int j = blockIdx.x * blockDim.x + threadIdx.x;
    if (j < 512) {
        float s = 0.f;
        const float* p = cb + j * 256;
        for (int c = 0; c < 256; c++) s = __fadd_rn(s, __fmul_rn(p[c], p[c]));
        cn[j] = s;
    }
}

__global__ void fnorm_k(const float* __restrict__ ze, float* __restrict__ fn, int HW)
{
    int w = (blockIdx.x * blockDim.x + threadIdx.x) >> 5;
    int lane = threadIdx.x & 31;
    int n = w / HW, hw = w - n * HW;
    const float* base = ze + (size_t)n * 256 * HW + hw;
    float s = 0.f;
    for (int k = lane; k < 256; k += 32) {
        float v = base[(size_t)k * HW];
        s = __fadd_rn(s, __fmul_rn(v, v));
    }
    #pragma unroll
    for (int o = 16; o > 0; o >>= 1) s += __shfl_down_sync(0xffffffffu, s, o);
    if (lane == 0) fn[w] = s;
}

#define VQ_KC 16
__global__ void __launch_bounds__(512) vq_dist_argmin(
    const float* __restrict__ ze, const float* __restrict__ cbT,
    const float* __restrict__ cn, const float* __restrict__ fnorm,
    int* __restrict__ idx, int HW)
{
    __shared__ float fs[64 * 17];
    __shared__ __align__(16) float cbs[VQ_KC * 512];
    __shared__ float cns[512];
    __shared__ float rd[64 * 8];
    __shared__ int   rj[64 * 8];

    const int t = threadIdx.x, px = t & 63, jg = t >> 6;
    const int p = blockIdx.x * 64 + px;
    cns[t] = cn[t];

    float acc[64];
    #pragma unroll
    for (int j = 0; j < 64; j++) acc[j] = 0.f;

    for (int k0 = 0; k0 < 256; k0 += VQ_KC) {
        __syncthreads();
        for (int i = t; i < 64 * VQ_KC; i += 512) {
            int kk = i >> 6, pp = i & 63;
            int gp = blockIdx.x * 64 + pp;
            int gn = gp / HW, ghw = gp - gn * HW;
            fs[pp * 17 + kk] = ze[((size_t)gn * 256 + (k0 + kk)) * HW + ghw];
        }
        for (int i = t; i < VQ_KC * 512; i += 512)
            cbs[i] = cbT[(size_t)(k0 + (i >> 9)) * 512 + (i & 511)];
        __syncthreads();

        float fv[VQ_KC];
        #pragma unroll
        for (int kk = 0; kk < VQ_KC; kk++) fv[kk] = fs[px * 17 + kk];

        #pragma unroll
        for (int j4 = 0; j4 < 16; j4++) {
            float a0, a1, a2, a3;
            {
                float4 c = *(const float4*)&cbs[jg * 64 + j4 * 4];
                a0 = __fmul_rn(fv[0], c.x); a1 = __fmul_rn(fv[0], c.y);
                a2 = __fmul_rn(fv[0], c.z); a3 = __fmul_rn(fv[0], c.w);
                #pragma unroll
                for (int kk = 1; kk < 8; kk++) {
                    float4 d = *(const float4*)&cbs[kk * 512 + jg * 64 + j4 * 4];
                    a0 = fmaf(fv[kk], d.x, a0); a1 = fmaf(fv[kk], d.y, a1);
                    a2 = fmaf(fv[kk], d.z, a2); a3 = fmaf(fv[kk], d.w, a3);
                }
                acc[j4*4+0] = __fadd_rn(acc[j4*4+0], a0);
                acc[j4*4+1] = __fadd_rn(acc[j4*4+1], a1);
                acc[j4*4+2] = __fadd_rn(acc[j4*4+2], a2);
                acc[j4*4+3] = __fadd_rn(acc[j4*4+3], a3);
            }
            {
                float4 c = *(const float4*)&cbs[8 * 512 + jg * 64 + j4 * 4];
                a0 = __fmul_rn(fv[8], c.x); a1 = __fmul_rn(fv[8], c.y);
                a2 = __fmul_rn(fv[8], c.z); a3 = __fmul_rn(fv[8], c.w);
                #pragma unroll
                for (int kk = 9; kk < 16; kk++) {
                    float4 d = *(const float4*)&cbs[kk * 512 + jg * 64 + j4 * 4];
                    a0 = fmaf(fv[kk], d.x, a0); a1 = fmaf(fv[kk], d.y, a1);
                    a2 = fmaf(fv[kk], d.z, a2); a3 = fmaf(fv[kk], d.w, a3);
                }
                acc[j4*4+0] = __fadd_rn(acc[j4*4+0], a0);
                acc[j4*4+1] = __fadd_rn(acc[j4*4+1], a1);
                acc[j4*4+2] = __fadd_rn(acc[j4*4+2], a2);
                acc[j4*4+3] = __fadd_rn(acc[j4*4+3], a3);
            }
        }
    }

    float S = fnorm[p];
    float best = 3.4028235e38f;
    int bj = 0;
    #pragma unroll
    for (int j = 0; j < 64; j++) {
        float q = __fsub_rn(S, __fmul_rn(2.0f, acc[j]));
        float dj = __fadd_rn(q, cns[jg * 64 + j]);
        if (dj < best) { best = dj; bj = jg * 64 + j; }
    }
    rd[px * 8 + jg] = best;
    rj[px * 8 + jg] = bj;
    __syncthreads();
    if (t < 64) {
        float bb = rd[t * 8]; int jj = rj[t * 8];
        #pragma unroll
        for (int gsel = 1; gsel < 8; gsel++) {
            float d2 = rd[t * 8 + gsel];
            if (d2 < bb) { bb = d2; jj = rj[t * 8 + gsel]; }
        }
        idx[blockIdx.x * 64 + t] = jj;
    }
}

__global__ void vq_gather(const int* __restrict__ idx, const float* __restrict__ cb,
                          float* __restrict__ zq, int HW, int total)
{
    int stride = gridDim.x * blockDim.x;
    for (int i = blockIdx.x * blockDim.x + threadIdx.x; i < total; i += stride) {
        int hw = i % HW, nc = i / HW, c = nc & 255, n = nc >> 8;
        zq[i] = cb[idx[n * HW + hw] * 256 + c];
    }
}

// ---------------- pipeline ----------------
extern "C" void kernel_launch(void* const* d_in, const int* in_sizes, int n_in,
                              void* d_out, int out_size)
{
    const float* img  = (const float*)d_in[0];
    const float* e_w1 = (const float*)d_in[1];
    const float* e_g1 = (const float*)d_in[2];
    const float* e_b1 = (const float*)d_in[3];
    const float* e_w2 = (const float*)d_in[4];
    const float* e_g2 = (const float*)d_in[5];
    const float* e_b2 = (const float*)d_in[6];
    const float* e_w3 = (const float*)d_in[7];
    const float* e_g3 = (const float*)d_in[8];
    const float* e_b3 = (const float*)d_in[9];
    const float* e_w4 = (const float*)d_in[10];
    const float* e_g4 = (const float*)d_in[12];
    const float* e_b4 = (const float*)d_in[13];
    const float* e_g5 = (const float*)d_in[14];
    const float* e_b5 = (const float*)d_in[15];
    const float* cb   = (const float*)d_in[16];
    const float* dw1  = (const float*)d_in[17];
    const float* dg1  = (const float*)d_in[18];
    const float* db1  = (const float*)d_in[19];
    const float* dw2  = (const float*)d_in[20];
    const float* dg2  = (const float*)d_in[21];
    const float* db2  = (const float*)d_in[22];
    const float* dg3  = (const float*)d_in[23];
    const float* db3  = (const float*)d_in[24];
    const float* dt1  = (const float*)d_in[25];
    const float* dg4  = (const float*)d_in[26];
    const float* db4  = (const float*)d_in[27];
    const float* dt2  = (const float*)d_in[28];
    const float* dg5  = (const float*)d_in[30];
    const float* db5  = (const float*)d_in[31];
    float* out = (float*)d_out;

    float *buf128, *b64a, *b64b, *b64c, *mean, *istd, *cnorm, *fnorm, *cbT;
    int* idx;
    cudaGetSymbolAddress((void**)&buf128, g_buf128);
    cudaGetSymbolAddress((void**)&b64a,   g_b64a);
    cudaGetSymbolAddress((void**)&b64b,   g_b64b);
    cudaGetSymbolAddress((void**)&b64c,   g_b64c);
    cudaGetSymbolAddress((void**)&mean,   g_mean);
    cudaGetSymbolAddress((void**)&istd,   g_istd);
    cudaGetSymbolAddress((void**)&cnorm,  g_cnorm);
    cudaGetSymbolAddress((void**)&fnorm,  g_fnorm);
    cudaGetSymbolAddress((void**)&cbT,    g_cbT);
    cudaGetSymbolAddress((void**)&idx,    g_idx);

    const int T128 = 33554432, T64 = 8388608;

    // ---- encoder ----
    conv_gemm128<<<dim3(1024, 2), 256>>>(e_w1, img, buf128, 256, 3, 16, 4, 2, 1, 256, 256, 128, 128);
    bn_stats<<<256, 256>>>(buf128, (const float*)0, mean, istd, 256, 16384, 8);
    bn_apply<<<16384, 256>>>(buf128, (const float*)0, buf128, e_g1, e_b1, mean, istd, 256, 16384, T128, 1);

    conv_gemm128<<<dim3(256, 2), 256>>>(e_w2, buf128, b64a, 256, 256, 16, 4, 2, 1, 128, 128, 64, 64);
    bn_stats<<<256, 256>>>(b64a, (const float*)0, mean, istd, 256, 4096, 8);
    bn_apply<<<8192, 256>>>(b64a, (const float*)0, b64a, e_g2, e_b2, mean, istd, 256, 4096, T64, 1);

    conv_gemm128<<<dim3(256, 2), 256>>>(e_w3, b64a, b64b, 256, 256, 9, 3, 1, 1, 64, 64, 64, 64);
    bn_stats<<<256, 256>>>(b64b, (const float*)0, mean, istd, 256, 4096, 8);
    bn_apply<<<8192, 256>>>(b64b, (const float*)0, b64b, e_g3, e_b3, mean, istd, 256, 4096, T64, 1);

    conv_gemm128<<<dim3(256, 2), 256>>>(e_w4, b64b, b64c, 256, 256, 1, 1, 1, 0, 64, 64, 64, 64);
    bn_stats<<<256, 256>>>(b64c, (const float*)0, mean, istd, 256, 4096, 8);
    bn_apply<<<8192, 256>>>(b64c, (const float*)0, b64c, e_g4, e_b4, mean, istd, 256, 4096, T64, 1);

    bn_stats<<<256, 256>>>(b64a, b64c, mean, istd, 256, 4096, 8);
    bn_apply<<<8192, 256>>>(b64a, b64c, b64b, e_g5, e_b5, mean, istd, 256, 4096, T64, 0);

    // ---- VQ ----
    transpose_cb<<<512, 256>>>(cb, cbT);
    cnorm_k<<<2, 256>>>(cb, cnorm);
    fnorm_k<<<4096, 256>>>(b64b, fnorm, 4096);
    vq_dist_argmin<<<512, 512>>>(b64b, cbT, cnorm, fnorm, idx, 4096);
    vq_gather<<<8192, 256>>>(idx, cb, b64c, 4096, T64);

    // ---- decoder ----
    conv_gemm128<<<dim3(256, 2), 256>>>(dw1, b64c, b64a, 256, 256, 9, 3, 1, 1, 64, 64, 64, 64);
    bn_stats<<<256, 256>>>(b64a, (const float*)0, mean, istd, 256, 4096, 8);
    bn_apply<<<8192, 256>>>(b64a, (const float*)0, b64a, dg1, db1, mean, istd, 256, 4096, T64, 1);

    conv_gemm128<<<dim3(256, 2), 256>>>(dw2, b64a, b64b, 256, 256, 1, 1, 1, 0, 64, 64, 64, 64);
    bn_stats<<<256, 256>>>(b64b, (const float*)0, mean, istd, 256, 4096, 8);
    bn_apply<<<8192, 256>>>(b64b, (const float*)0, b64b, dg2, db2, mean, istd, 256, 4096, T64, 1);

    bn_stats<<<256, 256>>>(b64c, b64b, mean, istd, 256, 4096, 8);
    bn_apply<<<8192, 256>>>(b64c, b64b, b64a, dg3, db3, mean, istd, 256, 4096, T64, 1);

    convt_gemm128<<<dim3(256, 2, 4), 256>>>(dt1, b64a, buf128, 256, 256, 64, 64, 128, 128);
    bn_stats<<<256, 256>>>(buf128, (const float*)0, mean, istd, 256, 16384, 8);
    bn_apply<<<16384, 256>>>(buf128, (const float*)0, buf128, dg4, db4, mean, istd, 256, 16384, T128, 1);

    convt_direct<<<dim3(256, 3, 8), 256>>>(dt2, buf128, out, 3, 256, 128, 128, 256, 256);
    bn_stats<<<3, 256>>>(out, (const float*)0, mean, istd, 3, 65536, 8);
    bn_apply<<<1536, 256>>>(out, (const float*)0, out, dg5, db5, mean, istd, 3, 65536, 1572864, 2);
}